// round 15
// baseline (speedup 1.0000x reference)
#include <cuda_runtime.h>
#include <cuda_fp16.h>
#include <math.h>
#include <stdint.h>

#define CLAMP_V 10000.0f
#define EPS_V   1e-8f
#define C_DIM   1024
#define H_DIM   4
#define DH      256
#define S_MAX   18
#define SH_N    72          // S*H
#define SH_P    80          // padded to 5 m16 tiles
#define NCAP    100352
#define NPCAP   (NCAP/2)
#define NCH     (C_DIM/32)  // 32 k-chunks in pass 1

// ------------------------- device scratch (static, no allocs) ----------------
__device__ float    g_qp[S_MAX * C_DIM];
__device__ __align__(16) uint2    g_Bph[64 * SH_N * 4];           // fp16x2 B k-pairs [g][sh][j]
__device__ __align__(16) unsigned g_Wph[(size_t)NPCAP * SH_P];    // fp16x2 (w[2p], w[2p+1]) [npair][sh]
__device__ __align__(16) unsigned g_Xh[(size_t)NPCAP * C_DIM];    // fp16x2 (x[2p][c], x[2p+1][c])
__device__ float    g_Z[SH_N];
__device__ float    g_u[SH_N * C_DIM];
__device__ float    g_ubar[H_DIM * C_DIM];
__device__ float    g_obar[C_DIM];

// ------------------------------- helpers -------------------------------------
__device__ __forceinline__ float san(float v) {
    if (!(v == v)) return 0.f;
    return fminf(fmaxf(v, -CLAMP_V), CLAMP_V);
}
__device__ __forceinline__ unsigned pack_h2(float lo, float hi) {
    unsigned r;
    asm("cvt.rn.f16x2.f32 %0, %1, %2;" : "=r"(r) : "f"(hi), "f"(lo));
    return r;
}
__device__ __forceinline__ void mma16h(float d[4], const unsigned a[4], const unsigned b[2]) {
    asm volatile(
        "mma.sync.aligned.m16n8k16.row.col.f32.f16.f16.f32 "
        "{%0,%1,%2,%3},{%4,%5,%6,%7},{%8,%9},{%0,%1,%2,%3};\n"
        : "+f"(d[0]), "+f"(d[1]), "+f"(d[2]), "+f"(d[3])
        : "r"(a[0]), "r"(a[1]), "r"(a[2]), "r"(a[3]), "r"(b[0]), "r"(b[1]));
}
__device__ __forceinline__ void red2(float* p, float a, float b) {
    asm volatile("red.global.add.v2.f32 [%0], {%1, %2};" :: "l"(p), "f"(a), "f"(b) : "memory");
}
#define CPA16(dst, src) asm volatile("cp.async.cg.shared.global [%0], [%1], 16;" :: "r"(dst), "l"(src))
#define CPA_COMMIT()    asm volatile("cp.async.commit_group;")
#define CPA_WAIT1()     asm volatile("cp.async.wait_group 1;" ::: "memory")

__device__ __forceinline__ float block_reduce_sum(float v, float* red8) {
    #pragma unroll
    for (int o = 16; o > 0; o >>= 1) v += __shfl_xor_sync(0xffffffffu, v, o);
    int w = threadIdx.x >> 5, lane = threadIdx.x & 31;
    if (lane == 0) red8[w] = v;
    __syncthreads();
    float tot = 0.f;
    #pragma unroll
    for (int i = 0; i < 8; i++) tot += red8[i];
    return tot;
}

// ------------------------------- kernels -------------------------------------
// qp[s][j] = ( rmsnorm(seeds[s], w_nq) . Wq[j] + bq[j] ) / 16
__global__ void __launch_bounds__(256) k_qp(const float* __restrict__ seeds,
                                            const float* __restrict__ w_nq,
                                            const float* __restrict__ ipw,
                                            const float* __restrict__ ipb, int S) {
    extern __shared__ __align__(16) float qs[];   // [S][1024]
    int t = threadIdx.x;
    int wj = t >> 5, lane = t & 31;
    for (int i = blockIdx.x * 256 + t; i < SH_N * C_DIM; i += 128 * 256) g_u[i] = 0.f;
    if (blockIdx.x == 0 && t < SH_N) g_Z[t] = 0.f;
    for (int s = wj; s < S; s += 8) {
        const float4* src = (const float4*)(seeds + (size_t)s * C_DIM);
        float4 v[8];
        float ssq = 0.f;
        #pragma unroll
        for (int i = 0; i < 8; i++) {
            float4 a = src[lane + i * 32];
            a.x = san(a.x); a.y = san(a.y); a.z = san(a.z); a.w = san(a.w);
            v[i] = a;
            ssq += a.x * a.x + a.y * a.y + a.z * a.z + a.w * a.w;
        }
        #pragma unroll
        for (int o = 16; o > 0; o >>= 1) ssq += __shfl_xor_sync(0xffffffffu, ssq, o);
        float inv = 1.f / (sqrtf(ssq) * (1.0f / 32.0f) + EPS_V);
        #pragma unroll
        for (int i = 0; i < 8; i++) {
            float4 wn = ((const float4*)w_nq)[lane + i * 32];
            float4 o = make_float4(v[i].x * wn.x * inv, v[i].y * wn.y * inv,
                                   v[i].z * wn.z * inv, v[i].w * wn.w * inv);
            ((float4*)(qs + s * C_DIM))[lane + i * 32] = o;
        }
    }
    __syncthreads();
    int j = blockIdx.x * 8 + wj;
    const float4* wr = (const float4*)(ipw + (size_t)j * C_DIM);
    float acc[S_MAX];
    #pragma unroll
    for (int s = 0; s < S_MAX; s++) acc[s] = 0.f;
    for (int c4 = 0; c4 < 8; c4++) {
        float4 a = wr[lane + c4 * 32];
        int cb = (lane + c4 * 32) * 4;
        for (int s = 0; s < S; s++) {
            float4 b = *(const float4*)&qs[s * C_DIM + cb];
            acc[s] += a.x * b.x + a.y * b.y + a.z * b.z + a.w * b.w;
        }
    }
    for (int s = 0; s < S; s++) {
        float v = acc[s];
        #pragma unroll
        for (int o = 16; o > 0; o >>= 1) v += __shfl_xor_sync(0xffffffffu, v, o);
        if (lane == 0) g_qp[s * C_DIM + j] = (v + ipb[j]) * 0.0625f;
    }
}

// B[sh][c] = w_nkv[c] * sum_d qp[s][h*DH+d] * Wk[h*DH+d][c]  -> fp16x2 k-pair frags
__global__ void __launch_bounds__(256) k_bmat(const float* __restrict__ ipw,
                                              const float* __restrict__ w_nkv, int S) {
    extern __shared__ __align__(16) float sm[];
    float* qph = sm;                                   // [S*4][256] : sh-major
    float (*psum)[S_MAX][16] = (float (*)[S_MAX][16])(sm + S_MAX * 4 * DH);
    int t = threadIdx.x;
    int c_l = t & 15, seg = t >> 4;
    int g = blockIdx.x;
    int cb = g * 16;
    for (int i = t; i < S * 4 * DH; i += 256) {
        int sh = i >> 8, d = i & 255;
        int s = sh >> 2, h = sh & 3;
        qph[i] = g_qp[s * C_DIM + h * DH + d];
    }
    __syncthreads();
    int h = seg >> 2;
    int dloc = (seg & 3) * 64;
    int dbase = h * DH + dloc;
    float acc[S_MAX];
    #pragma unroll
    for (int s = 0; s < S_MAX; s++) acc[s] = 0.f;
    const float* wkb = ipw + ((size_t)C_DIM + dbase) * C_DIM + cb + c_l;
    for (int d4 = 0; d4 < 16; d4++) {
        int d0 = d4 * 4;
        float k0 = wkb[(size_t)(d0 + 0) * C_DIM];
        float k1 = wkb[(size_t)(d0 + 1) * C_DIM];
        float k2 = wkb[(size_t)(d0 + 2) * C_DIM];
        float k3 = wkb[(size_t)(d0 + 3) * C_DIM];
        for (int s = 0; s < S; s++) {
            float4 q = *(const float4*)&qph[(s * 4 + h) * DH + dloc + d0];
            acc[s] += q.x * k0 + q.y * k1 + q.z * k2 + q.w * k3;
        }
    }
    for (int s = 0; s < S; s++) psum[seg][s][c_l] = acc[s];
    __syncthreads();
    for (int p = t; p < SH_N * 4; p += 256) {
        int sh = p >> 2, j = p & 3;
        int s = sh >> 2, hh = sh & 3;
        float v0 = 0.f, v1 = 0.f, v2 = 0.f, v3 = 0.f;
        #pragma unroll
        for (int k = 0; k < 4; k++) {
            v0 += psum[hh * 4 + k][s][2 * j];
            v1 += psum[hh * 4 + k][s][2 * j + 1];
            v2 += psum[hh * 4 + k][s][2 * j + 8];
            v3 += psum[hh * 4 + k][s][2 * j + 9];
        }
        v0 *= w_nkv[cb + 2 * j];     v1 *= w_nkv[cb + 2 * j + 1];
        v2 *= w_nkv[cb + 2 * j + 8]; v3 *= w_nkv[cb + 2 * j + 9];
        g_Bph[((size_t)g * SH_N + sh) * 4 + j] = make_uint2(pack_h2(v0, v1), pack_h2(v2, v3));
    }
}

// Pass 1: 128 rows/block, warp m16 tile, fp16 m16n8k16 MMA, 4 CTAs/SM.
// Dumps fp16 row-pair-packed X (g_Xh) per chunk for pass 2.
// Epilogue packs adjacent-row fp16 weight pairs into g_Wph + Z partials.
#define XS_BYTES (2 * 128 * 36 * 4)                 // 36864
#define BS_BYTES (2 * 2 * SH_N * 4 * 8)             // 9216
#define SMEM_SC  (XS_BYTES + BS_BYTES)              // 46080
__global__ void __launch_bounds__(256, 4) k_scores(const float* __restrict__ x, int N) {
    extern __shared__ __align__(16) char smem[];
    float (*Xs)[128][36] = (float (*)[128][36])smem;
    uint2 (*Bs)[2][SH_N][4] = (uint2 (*)[2][SH_N][4])(smem + XS_BYTES);
    __shared__ float zs[8][SH_N];
    int t = threadIdx.x, w = t >> 5, lane = t & 31;
    int q = lane >> 2, j = lane & 3;
    size_t base = (size_t)blockIdx.x * 128;
    size_t lastRow = (size_t)N - 1;
    int r0 = w * 16 + q;

    bool ok[2];
    ok[0] = (base + r0) < (size_t)N;
    ok[1] = (base + r0 + 8) < (size_t)N;

    float acc[9][4];
    #pragma unroll
    for (int n = 0; n < 9; n++)
        #pragma unroll
        for (int i = 0; i < 4; i++) acc[n][i] = 0.f;
    float ssq[2] = {0.f, 0.f};

    auto stage = [&](int ch, int b) {
        unsigned xd = (unsigned)__cvta_generic_to_shared(&Xs[b][0][0]);
        int k0 = ch * 32;
        #pragma unroll
        for (int it = 0; it < 4; it++) {
            int idx = t + it * 256;
            int row = idx >> 3, seg = idx & 7;
            size_t gr = base + row; if (gr > lastRow) gr = lastRow;
            CPA16(xd + (unsigned)(row * 36 + seg * 4) * 4,
                  (const char*)(x + gr * C_DIM + k0 + seg * 4));
        }
        const char* src = (const char*)(g_Bph + (size_t)ch * 2 * SH_N * 4);
        unsigned bd = (unsigned)__cvta_generic_to_shared(&(*Bs)[0][0][0]) + b * (BS_BYTES / 2);
        CPA16(bd + t * 16, src + t * 16);
        if (t < 32) CPA16(bd + (t + 256) * 16, src + (t + 256) * 16);
    };

    stage(0, 0);
    CPA_COMMIT();
    for (int ch = 0; ch < NCH; ch++) {
        int buf = ch & 1;
        if (ch + 1 < NCH) stage(ch + 1, buf ^ 1);
        CPA_COMMIT();
        CPA_WAIT1();
        __syncthreads();
        #pragma unroll
        for (int s = 0; s < 2; s++) {          // two k16 steps per 32-chunk
            int cb = s * 16 + 2 * j;
            float2 x00 = *(const float2*)&Xs[buf][r0][cb];
            float2 x01 = *(const float2*)&Xs[buf][r0][cb + 8];
            float2 x10 = *(const float2*)&Xs[buf][r0 + 8][cb];
            float2 x11 = *(const float2*)&Xs[buf][r0 + 8][cb + 8];
            ssq[0] += x00.x * x00.x + x00.y * x00.y + x01.x * x01.x + x01.y * x01.y;
            ssq[1] += x10.x * x10.x + x10.y * x10.y + x11.x * x11.x + x11.y * x11.y;
            unsigned a[4] = { pack_h2(x00.x, x00.y), pack_h2(x10.x, x10.y),
                              pack_h2(x01.x, x01.y), pack_h2(x11.x, x11.y) };
            #pragma unroll
            for (int nt = 0; nt < 9; nt++) {
                uint2 bb = Bs[buf][s][nt * 8 + q][j];
                unsigned b[2] = {bb.x, bb.y};
                mma16h(acc[nt], a, b);
            }
        }
        // dump fp16 row-pair X for pass 2 (64 npairs x 16 col-pairs = 1024 uint2 halves)
        {
            int k0 = ch * 32;
            #pragma unroll
            for (int it = 0; it < 4; it++) {
                int idx = t + it * 256;
                int p = idx >> 4, cp = idx & 15;
                float2 lo = *(const float2*)&Xs[buf][2 * p][2 * cp];
                float2 hi = *(const float2*)&Xs[buf][2 * p + 1][2 * cp];
                uint2 v = make_uint2(pack_h2(lo.x, hi.x), pack_h2(lo.y, hi.y));
                *(uint2*)&g_Xh[((base >> 1) + p) * C_DIM + k0 + 2 * cp] = v;
            }
        }
        __syncthreads();
    }

    float inv[2];
    #pragma unroll
    for (int s = 0; s < 2; s++) {
        float sv = ssq[s];
        sv += __shfl_xor_sync(0xffffffffu, sv, 1);
        sv += __shfl_xor_sync(0xffffffffu, sv, 2);
        inv[s] = 1.f / (sqrtf(sv) * (1.0f / 32.0f) + EPS_V);
    }

    // epilogue: e = exp(score); adjacent-row fp16 pairs into g_Wph; Z partials
    size_t npair_b = (base >> 1) + (size_t)w * 8 + (q >> 1);
    bool evenq = (q & 1) == 0;
    #pragma unroll
    for (int nt = 0; nt < 9; nt++) {
        int c0 = nt * 8 + 2 * j;
        float e00 = ok[0] ? __expf(acc[nt][0] * inv[0]) : 0.f;
        float e01 = ok[0] ? __expf(acc[nt][1] * inv[0]) : 0.f;
        float e10 = ok[1] ? __expf(acc[nt][2] * inv[1]) : 0.f;
        float e11 = ok[1] ? __expf(acc[nt][3] * inv[1]) : 0.f;
        float z0 = e00 + e10, z1 = e01 + e11;
        float w00 = e00 * inv[0], w01 = e01 * inv[0];
        float w10 = e10 * inv[1], w11 = e11 * inv[1];
        float p00 = __shfl_xor_sync(0xffffffffu, w00, 4);
        float p01 = __shfl_xor_sync(0xffffffffu, w01, 4);
        float p10 = __shfl_xor_sync(0xffffffffu, w10, 4);
        float p11 = __shfl_xor_sync(0xffffffffu, w11, 4);
        if (evenq) {
            g_Wph[npair_b * SH_P + c0]       = pack_h2(w00, p00);
            g_Wph[(npair_b + 4) * SH_P + c0] = pack_h2(w10, p10);
        } else {
            g_Wph[npair_b * SH_P + c0 + 1]       = pack_h2(p01, w01);
            g_Wph[(npair_b + 4) * SH_P + c0 + 1] = pack_h2(p11, w11);
        }
        #pragma unroll
        for (int o = 4; o < 32; o <<= 1) {
            z0 += __shfl_xor_sync(0xffffffffu, z0, o);
            z1 += __shfl_xor_sync(0xffffffffu, z1, o);
        }
        if (q == 0) { zs[w][c0] = z0; zs[w][c0 + 1] = z1; }
    }
    __syncthreads();
    if (t < SH_N) {
        float z = 0.f;
        #pragma unroll
        for (int i = 0; i < 8; i++) z += zs[i][t];
        atomicAdd(&g_Z[t], z);
    }
}

// Pass 2: u[sh][c] += sum_n wp[sh,n] * xs[n,c].  32-row chunks, fp16 m16n8k16 MMA,
// W and X both fp16 direct from prepacked buffers. 4 CTAs/SM, full-wave grid.
#define UY 74
__global__ void __launch_bounds__(256, 4) k_u(int N) {
    __shared__ __align__(16) unsigned Wh[2][16 * 88];   // fp16x2 [npair][sh] stride 88
    __shared__ __align__(16) unsigned Xh[2][16][136];   // fp16x2 row-pairs
    int t = threadIdx.x, w = t >> 5, lane = t & 31;
    int q = lane >> 2, j = lane & 3;
    int cbase = blockIdx.x * 128;
    int TC = N >> 5;
    int c0 = (int)((long long)blockIdx.y * TC / UY);
    int c1 = (int)((long long)(blockIdx.y + 1) * TC / UY);
    float acc[5][2][4];
    #pragma unroll
    for (int i = 0; i < 5; i++)
        #pragma unroll
        for (int k = 0; k < 2; k++)
            #pragma unroll
            for (int l = 0; l < 4; l++) acc[i][k][l] = 0.f;

    auto issue = [&](int ch, int b) {
        const char* wsrc = (const char*)(g_Wph + (size_t)ch * 16 * SH_P);
        unsigned wdst = (unsigned)__cvta_generic_to_shared(&Wh[b][0]);
        if (t < 256) {
            int np = t / 20, seg = t % 20;
            CPA16(wdst + (unsigned)(np * 88 + seg * 4) * 4,
                  wsrc + (np * 80 + seg * 4) * 4);
        }
        if (t < 64) {
            int i2 = t + 256;
            int np = i2 / 20, seg = i2 % 20;
            CPA16(wdst + (unsigned)(np * 88 + seg * 4) * 4,
                  wsrc + (np * 80 + seg * 4) * 4);
        }
        unsigned xdst = (unsigned)__cvta_generic_to_shared(&Xh[b][0][0]);
        #pragma unroll
        for (int it = 0; it < 2; it++) {
            int idx = t + it * 256;                 // 512 = 16 npairs x 32 16B-segs
            int p = idx >> 5, seg = idx & 31;
            const char* xsrc = (const char*)(g_Xh + ((size_t)ch * 16 + p) * C_DIM + cbase + seg * 4);
            CPA16(xdst + (unsigned)(p * 136 + seg * 4) * 4, xsrc);
        }
    };

    issue(c0, 0);
    CPA_COMMIT();
    for (int ch = c0; ch < c1; ch++) {
        int buf = (ch - c0) & 1;
        if (ch + 1 < c1) issue(ch + 1, buf ^ 1);
        CPA_COMMIT();
        CPA_WAIT1();
        __syncthreads();
        #pragma unroll
        for (int kg = 0; kg < 2; kg++) {
            int rA = kg * 8 + j, rB = rA + 4;
            unsigned b0[2] = { Xh[buf][rA][w * 16 + q],     Xh[buf][rB][w * 16 + q] };
            unsigned b1[2] = { Xh[buf][rA][w * 16 + 8 + q], Xh[buf][rB][w * 16 + 8 + q] };
            #pragma unroll
            for (int mt = 0; mt < 5; mt++) {
                int sh = mt * 16 + q;
                unsigned a[4];
                a[0] = Wh[buf][rA * 88 + sh];
                a[1] = Wh[buf][rA * 88 + sh + 8];
                a[2] = Wh[buf][rB * 88 + sh];
                a[3] = Wh[buf][rB * 88 + sh + 8];
                mma16h(acc[mt][0], a, b0);
                mma16h(acc[mt][1], a, b1);
            }
        }
        __syncthreads();
    }
    #pragma unroll
    for (int mt = 0; mt < 5; mt++) {
        int sh = mt * 16 + q;
        #pragma unroll
        for (int ct = 0; ct < 2; ct++) {
            int c = cbase + w * 16 + ct * 8 + 2 * j;
            if (sh < SH_N)
                red2(&g_u[sh * C_DIM + c], acc[mt][ct][0], acc[mt][ct][1]);
            if (sh + 8 < SH_N)
                red2(&g_u[(sh + 8) * C_DIM + c], acc[mt][ct][2], acc[mt][ct][3]);
        }
    }
}

// ubar[h][c] = w_nkv[c] * mean_s ( u[(s,h)][c] / Z[(s,h)] )
__global__ void k_ubar(const float* __restrict__ w_nkv, int S) {
    __shared__ float rzs[SH_N];
    int t = threadIdx.x;
    int i = blockIdx.x * 256 + t;
    if (t < SH_N) rzs[t] = 1.f / g_Z[t];
    __syncthreads();
    if (i >= H_DIM * C_DIM) return;
    int h = i >> 10, c = i & 1023;
    float s = 0.f;
    for (int si = 0; si < S; si++)
        s += g_u[(size_t)(si * H_DIM + h) * C_DIM + c] * rzs[si * H_DIM + h];
    g_ubar[i] = w_nkv[c] * s / (float)S;
}

// obar[j] = sum_c ubar[h][c] * Wv[2C+j][c] + bv[2C+j]
__global__ void k_obar(const float* __restrict__ ipw, const float* __restrict__ ipb) {
    __shared__ float red8[8];
    int j = blockIdx.x, t = threadIdx.x;
    int h = j >> 8;
    const float* wv = ipw + ((size_t)2 * C_DIM + j) * C_DIM;
    const float* ub = g_ubar + h * C_DIM;
    float acc = 0.f;
    for (int c = t; c < C_DIM; c += 256) acc += ub[c] * wv[c];
    float tot = block_reduce_sum(acc, red8);
    if (t == 0) g_obar[j] = tot + ipb[2 * C_DIM + j];
}

// out[c] = sanitize( sum_j obar[j] * Wout[c][j] + bout[c] )
__global__ void k_out(const float* __restrict__ opw, const float* __restrict__ opb,
                      float* __restrict__ out) {
    __shared__ float red8[8];
    int c = blockIdx.x, t = threadIdx.x;
    const float* wr = opw + (size_t)c * C_DIM;
    float acc = 0.f;
    for (int j = t; j < C_DIM; j += 256) acc += g_obar[j] * wr[j];
    float tot = block_reduce_sum(acc, red8);
    if (t == 0) out[c] = san(tot + opb[c]);
}

// ------------------------------- launcher ------------------------------------
extern "C" void kernel_launch(void* const* d_in, const int* in_sizes, int n_in,
                              void* d_out, int out_size) {
    const float* x     = (const float*)d_in[0];
    const float* seeds = (const float*)d_in[1];
    const float* w_nq  = (const float*)d_in[2];
    const float* w_nkv = (const float*)d_in[3];
    const float* ipw   = (const float*)d_in[4];
    const float* ipb   = (const float*)d_in[5];
    const float* opw   = (const float*)d_in[6];
    const float* opb   = (const float*)d_in[7];
    float* out = (float*)d_out;

    int N = in_sizes[0] / C_DIM;
    if (N > NCAP) N = NCAP;
    int S = in_sizes[1] / C_DIM;   // 18

    int qp_sm = S * C_DIM * 4;                        // 73728
    int bm_sm = S * 4 * DH * 4 + 16 * S_MAX * 16 * 4; // 92160
    cudaFuncSetAttribute(k_scores, cudaFuncAttributeMaxDynamicSharedMemorySize, SMEM_SC);
    cudaFuncSetAttribute(k_qp, cudaFuncAttributeMaxDynamicSharedMemorySize, qp_sm);
    cudaFuncSetAttribute(k_bmat, cudaFuncAttributeMaxDynamicSharedMemorySize, bm_sm);

    k_qp<<<C_DIM / 8, 256, qp_sm>>>(seeds, w_nq, ipw, ipb, S);
    k_bmat<<<C_DIM / 16, 256, bm_sm>>>(ipw, w_nkv, S);
    k_scores<<<(N + 127) / 128, 256, SMEM_SC>>>(x, N);
    k_u<<<dim3(8, UY), 256>>>(N);
    k_ubar<<<(H_DIM * C_DIM + 255) / 256, 256>>>(w_nkv, S);
    k_obar<<<C_DIM, 256>>>(ipw, ipb);
    k_out<<<C_DIM, 256>>>(opw, opb, out);
}

// round 16
// speedup vs baseline: 1.0628x; 1.0628x over previous
#include <cuda_runtime.h>
#include <cuda_fp16.h>
#include <math.h>
#include <stdint.h>

#define CLAMP_V 10000.0f
#define EPS_V   1e-8f
#define C_DIM   1024
#define H_DIM   4
#define DH      256
#define S_MAX   18
#define SH_N    72          // S*H
#define SH_P    80          // padded to 5 m16 tiles
#define NCAP    100352
#define NPCAP   (NCAP/2)
#define NCH     (C_DIM/32)  // 32 k-chunks in pass 1

// ------------------------- device scratch (static, no allocs) ----------------
__device__ float    g_qp[S_MAX * C_DIM];
__device__ __align__(16) uint2    g_Bph[64 * SH_N * 4];           // fp16x2 B k-pairs [g][sh][j]
__device__ __align__(16) unsigned g_Wph[(size_t)NPCAP * SH_P];    // fp16x2 (w[2p], w[2p+1]) [npair][sh]
__device__ float    g_Z[SH_N];
__device__ float    g_u[SH_N * C_DIM];
__device__ float    g_ubar[H_DIM * C_DIM];
__device__ float    g_obar[C_DIM];

// ------------------------------- helpers -------------------------------------
__device__ __forceinline__ float san(float v) {
    if (!(v == v)) return 0.f;
    return fminf(fmaxf(v, -CLAMP_V), CLAMP_V);
}
__device__ __forceinline__ unsigned pack_h2(float lo, float hi) {
    unsigned r;
    asm("cvt.rn.f16x2.f32 %0, %1, %2;" : "=r"(r) : "f"(hi), "f"(lo));
    return r;
}
__device__ __forceinline__ void mma16h(float d[4], const unsigned a[4], const unsigned b[2]) {
    asm volatile(
        "mma.sync.aligned.m16n8k16.row.col.f32.f16.f16.f32 "
        "{%0,%1,%2,%3},{%4,%5,%6,%7},{%8,%9},{%0,%1,%2,%3};\n"
        : "+f"(d[0]), "+f"(d[1]), "+f"(d[2]), "+f"(d[3])
        : "r"(a[0]), "r"(a[1]), "r"(a[2]), "r"(a[3]), "r"(b[0]), "r"(b[1]));
}
__device__ __forceinline__ void red2(float* p, float a, float b) {
    asm volatile("red.global.add.v2.f32 [%0], {%1, %2};" :: "l"(p), "f"(a), "f"(b) : "memory");
}
#define CPA16(dst, src) asm volatile("cp.async.cg.shared.global [%0], [%1], 16;" :: "r"(dst), "l"(src))
#define CPA_COMMIT()    asm volatile("cp.async.commit_group;")
#define CPA_WAIT1()     asm volatile("cp.async.wait_group 1;" ::: "memory")

__device__ __forceinline__ float block_reduce_sum(float v, float* red8) {
    #pragma unroll
    for (int o = 16; o > 0; o >>= 1) v += __shfl_xor_sync(0xffffffffu, v, o);
    int w = threadIdx.x >> 5, lane = threadIdx.x & 31;
    if (lane == 0) red8[w] = v;
    __syncthreads();
    float tot = 0.f;
    #pragma unroll
    for (int i = 0; i < 8; i++) tot += red8[i];
    return tot;
}

// ------------------------------- kernels -------------------------------------
// qp[s][j] = ( rmsnorm(seeds[s], w_nq) . Wq[j] + bq[j] ) / 16
__global__ void __launch_bounds__(256) k_qp(const float* __restrict__ seeds,
                                            const float* __restrict__ w_nq,
                                            const float* __restrict__ ipw,
                                            const float* __restrict__ ipb, int S) {
    extern __shared__ __align__(16) float qs[];   // [S][1024]
    int t = threadIdx.x;
    int wj = t >> 5, lane = t & 31;
    for (int i = blockIdx.x * 256 + t; i < SH_N * C_DIM; i += 128 * 256) g_u[i] = 0.f;
    if (blockIdx.x == 0 && t < SH_N) g_Z[t] = 0.f;
    for (int s = wj; s < S; s += 8) {
        const float4* src = (const float4*)(seeds + (size_t)s * C_DIM);
        float4 v[8];
        float ssq = 0.f;
        #pragma unroll
        for (int i = 0; i < 8; i++) {
            float4 a = src[lane + i * 32];
            a.x = san(a.x); a.y = san(a.y); a.z = san(a.z); a.w = san(a.w);
            v[i] = a;
            ssq += a.x * a.x + a.y * a.y + a.z * a.z + a.w * a.w;
        }
        #pragma unroll
        for (int o = 16; o > 0; o >>= 1) ssq += __shfl_xor_sync(0xffffffffu, ssq, o);
        float inv = 1.f / (sqrtf(ssq) * (1.0f / 32.0f) + EPS_V);
        #pragma unroll
        for (int i = 0; i < 8; i++) {
            float4 wn = ((const float4*)w_nq)[lane + i * 32];
            float4 o = make_float4(v[i].x * wn.x * inv, v[i].y * wn.y * inv,
                                   v[i].z * wn.z * inv, v[i].w * wn.w * inv);
            ((float4*)(qs + s * C_DIM))[lane + i * 32] = o;
        }
    }
    __syncthreads();
    int j = blockIdx.x * 8 + wj;
    const float4* wr = (const float4*)(ipw + (size_t)j * C_DIM);
    float acc[S_MAX];
    #pragma unroll
    for (int s = 0; s < S_MAX; s++) acc[s] = 0.f;
    for (int c4 = 0; c4 < 8; c4++) {
        float4 a = wr[lane + c4 * 32];
        int cb = (lane + c4 * 32) * 4;
        for (int s = 0; s < S; s++) {
            float4 b = *(const float4*)&qs[s * C_DIM + cb];
            acc[s] += a.x * b.x + a.y * b.y + a.z * b.z + a.w * b.w;
        }
    }
    for (int s = 0; s < S; s++) {
        float v = acc[s];
        #pragma unroll
        for (int o = 16; o > 0; o >>= 1) v += __shfl_xor_sync(0xffffffffu, v, o);
        if (lane == 0) g_qp[s * C_DIM + j] = (v + ipb[j]) * 0.0625f;
    }
}

// B[sh][c] = w_nkv[c] * sum_d qp[s][h*DH+d] * Wk[h*DH+d][c]  -> fp16x2 k-pair frags
// Grid (64, 2): y splits the seed dimension for 2x parallelism.
__global__ void __launch_bounds__(256) k_bmat(const float* __restrict__ ipw,
                                              const float* __restrict__ w_nkv, int S) {
    extern __shared__ __align__(16) float sm[];
    int half = (S + 1) >> 1;                           // 9
    int s0 = blockIdx.y * half;
    int s1 = s0 + half; if (s1 > S) s1 = S;
    int ls = s1 - s0;
    float* qph = sm;                                   // [ls*4][256] : local sh-major
    float (*psum)[9][16] = (float (*)[9][16])(sm + (size_t)half * 4 * DH);
    int t = threadIdx.x;
    int c_l = t & 15, seg = t >> 4;
    int g = blockIdx.x;
    int cb = g * 16;
    for (int i = t; i < ls * 4 * DH; i += 256) {
        int sh = i >> 8, d = i & 255;
        int s = s0 + (sh >> 2), h = sh & 3;
        qph[i] = g_qp[s * C_DIM + h * DH + d];
    }
    __syncthreads();
    int h = seg >> 2;
    int dloc = (seg & 3) * 64;
    int dbase = h * DH + dloc;
    float acc[9];
    #pragma unroll
    for (int s = 0; s < 9; s++) acc[s] = 0.f;
    const float* wkb = ipw + ((size_t)C_DIM + dbase) * C_DIM + cb + c_l;
    for (int d4 = 0; d4 < 16; d4++) {
        int d0 = d4 * 4;
        float k0 = wkb[(size_t)(d0 + 0) * C_DIM];
        float k1 = wkb[(size_t)(d0 + 1) * C_DIM];
        float k2 = wkb[(size_t)(d0 + 2) * C_DIM];
        float k3 = wkb[(size_t)(d0 + 3) * C_DIM];
        for (int s = 0; s < ls; s++) {
            float4 q = *(const float4*)&qph[(s * 4 + h) * DH + dloc + d0];
            acc[s] += q.x * k0 + q.y * k1 + q.z * k2 + q.w * k3;
        }
    }
    for (int s = 0; s < ls; s++) psum[seg][s][c_l] = acc[s];
    __syncthreads();
    for (int p = t; p < ls * 4 * 4; p += 256) {
        int shl = p >> 2, j = p & 3;
        int sl = shl >> 2, hh = shl & 3;
        int sh = (s0 + sl) * 4 + hh;
        float v0 = 0.f, v1 = 0.f, v2 = 0.f, v3 = 0.f;
        #pragma unroll
        for (int k = 0; k < 4; k++) {
            v0 += psum[hh * 4 + k][sl][2 * j];
            v1 += psum[hh * 4 + k][sl][2 * j + 1];
            v2 += psum[hh * 4 + k][sl][2 * j + 8];
            v3 += psum[hh * 4 + k][sl][2 * j + 9];
        }
        v0 *= w_nkv[cb + 2 * j];     v1 *= w_nkv[cb + 2 * j + 1];
        v2 *= w_nkv[cb + 2 * j + 8]; v3 *= w_nkv[cb + 2 * j + 9];
        g_Bph[((size_t)g * SH_N + sh) * 4 + j] = make_uint2(pack_h2(v0, v1), pack_h2(v2, v3));
    }
}

// Pass 1: 128 rows/block, warp m16 tile, fp16 m16n8k16 MMA, 4 CTAs/SM.
// Epilogue packs adjacent-row fp16 weight pairs into g_Wph + Z partials.
#define XS_BYTES (2 * 128 * 36 * 4)                 // 36864
#define BS_BYTES (2 * 2 * SH_N * 4 * 8)             // 9216
#define SMEM_SC  (XS_BYTES + BS_BYTES)              // 46080
__global__ void __launch_bounds__(256, 4) k_scores(const float* __restrict__ x, int N) {
    extern __shared__ __align__(16) char smem[];
    float (*Xs)[128][36] = (float (*)[128][36])smem;
    uint2 (*Bs)[2][SH_N][4] = (uint2 (*)[2][SH_N][4])(smem + XS_BYTES);
    __shared__ float zs[8][SH_N];
    int t = threadIdx.x, w = t >> 5, lane = t & 31;
    int q = lane >> 2, j = lane & 3;
    size_t base = (size_t)blockIdx.x * 128;
    size_t lastRow = (size_t)N - 1;
    int r0 = w * 16 + q;

    bool ok[2];
    ok[0] = (base + r0) < (size_t)N;
    ok[1] = (base + r0 + 8) < (size_t)N;

    float acc[9][4];
    #pragma unroll
    for (int n = 0; n < 9; n++)
        #pragma unroll
        for (int i = 0; i < 4; i++) acc[n][i] = 0.f;
    float ssq[2] = {0.f, 0.f};

    auto stage = [&](int ch, int b) {
        unsigned xd = (unsigned)__cvta_generic_to_shared(&Xs[b][0][0]);
        int k0 = ch * 32;
        #pragma unroll
        for (int it = 0; it < 4; it++) {
            int idx = t + it * 256;
            int row = idx >> 3, seg = idx & 7;
            size_t gr = base + row; if (gr > lastRow) gr = lastRow;
            CPA16(xd + (unsigned)(row * 36 + seg * 4) * 4,
                  (const char*)(x + gr * C_DIM + k0 + seg * 4));
        }
        const char* src = (const char*)(g_Bph + (size_t)ch * 2 * SH_N * 4);
        unsigned bd = (unsigned)__cvta_generic_to_shared(&(*Bs)[0][0][0]) + b * (BS_BYTES / 2);
        CPA16(bd + t * 16, src + t * 16);
        if (t < 32) CPA16(bd + (t + 256) * 16, src + (t + 256) * 16);
    };

    stage(0, 0);
    CPA_COMMIT();
    for (int ch = 0; ch < NCH; ch++) {
        int buf = ch & 1;
        if (ch + 1 < NCH) stage(ch + 1, buf ^ 1);
        CPA_COMMIT();
        CPA_WAIT1();
        __syncthreads();
        #pragma unroll
        for (int s = 0; s < 2; s++) {          // two k16 steps per 32-chunk
            int cb = s * 16 + 2 * j;
            float2 x00 = *(const float2*)&Xs[buf][r0][cb];
            float2 x01 = *(const float2*)&Xs[buf][r0][cb + 8];
            float2 x10 = *(const float2*)&Xs[buf][r0 + 8][cb];
            float2 x11 = *(const float2*)&Xs[buf][r0 + 8][cb + 8];
            ssq[0] += x00.x * x00.x + x00.y * x00.y + x01.x * x01.x + x01.y * x01.y;
            ssq[1] += x10.x * x10.x + x10.y * x10.y + x11.x * x11.x + x11.y * x11.y;
            unsigned a[4] = { pack_h2(x00.x, x00.y), pack_h2(x10.x, x10.y),
                              pack_h2(x01.x, x01.y), pack_h2(x11.x, x11.y) };
            #pragma unroll
            for (int nt = 0; nt < 9; nt++) {
                uint2 bb = Bs[buf][s][nt * 8 + q][j];
                unsigned b[2] = {bb.x, bb.y};
                mma16h(acc[nt], a, b);
            }
        }
        __syncthreads();
    }

    float inv[2];
    #pragma unroll
    for (int s = 0; s < 2; s++) {
        float sv = ssq[s];
        sv += __shfl_xor_sync(0xffffffffu, sv, 1);
        sv += __shfl_xor_sync(0xffffffffu, sv, 2);
        inv[s] = 1.f / (sqrtf(sv) * (1.0f / 32.0f) + EPS_V);
    }

    // epilogue: e = exp(score); adjacent-row fp16 pairs into g_Wph; Z partials
    size_t npair_b = (base >> 1) + (size_t)w * 8 + (q >> 1);
    bool evenq = (q & 1) == 0;
    #pragma unroll
    for (int nt = 0; nt < 9; nt++) {
        int c0 = nt * 8 + 2 * j;
        float e00 = ok[0] ? __expf(acc[nt][0] * inv[0]) : 0.f;
        float e01 = ok[0] ? __expf(acc[nt][1] * inv[0]) : 0.f;
        float e10 = ok[1] ? __expf(acc[nt][2] * inv[1]) : 0.f;
        float e11 = ok[1] ? __expf(acc[nt][3] * inv[1]) : 0.f;
        float z0 = e00 + e10, z1 = e01 + e11;
        float w00 = e00 * inv[0], w01 = e01 * inv[0];
        float w10 = e10 * inv[1], w11 = e11 * inv[1];
        float p00 = __shfl_xor_sync(0xffffffffu, w00, 4);
        float p01 = __shfl_xor_sync(0xffffffffu, w01, 4);
        float p10 = __shfl_xor_sync(0xffffffffu, w10, 4);
        float p11 = __shfl_xor_sync(0xffffffffu, w11, 4);
        if (evenq) {
            g_Wph[npair_b * SH_P + c0]       = pack_h2(w00, p00);
            g_Wph[(npair_b + 4) * SH_P + c0] = pack_h2(w10, p10);
        } else {
            g_Wph[npair_b * SH_P + c0 + 1]       = pack_h2(p01, w01);
            g_Wph[(npair_b + 4) * SH_P + c0 + 1] = pack_h2(p11, w11);
        }
        #pragma unroll
        for (int o = 4; o < 32; o <<= 1) {
            z0 += __shfl_xor_sync(0xffffffffu, z0, o);
            z1 += __shfl_xor_sync(0xffffffffu, z1, o);
        }
        if (q == 0) { zs[w][c0] = z0; zs[w][c0 + 1] = z1; }
    }
    __syncthreads();
    if (t < SH_N) {
        float z = 0.f;
        #pragma unroll
        for (int i = 0; i < 8; i++) z += zs[i][t];
        atomicAdd(&g_Z[t], z);
    }
}

// Pass 2: u[sh][c] += sum_n wp[sh,n] * xs[n,c].  32-row chunks, fp16 m16n8k16 MMA,
// W fp16 from smem, B-frags packed inline from f32 stage (stride 140: conflict-free).
#define UY 74
__global__ void __launch_bounds__(256, 4) k_u(const float* __restrict__ x, int N) {
    __shared__ __align__(16) unsigned Wh[2][16 * 88];   // fp16x2 [npair][sh] stride 88, 11 KB
    __shared__ __align__(16) float Xs[2][32][140];      // f32 staging, 35.8 KB
    int t = threadIdx.x, w = t >> 5, lane = t & 31;
    int q = lane >> 2, j = lane & 3;
    int cbase = blockIdx.x * 128;
    int TC = N >> 5;
    int c0 = (int)((long long)blockIdx.y * TC / UY);
    int c1 = (int)((long long)(blockIdx.y + 1) * TC / UY);
    float acc[5][2][4];
    #pragma unroll
    for (int i = 0; i < 5; i++)
        #pragma unroll
        for (int k = 0; k < 2; k++)
            #pragma unroll
            for (int l = 0; l < 4; l++) acc[i][k][l] = 0.f;

    auto issue = [&](int ch, int b) {
        const char* wsrc = (const char*)(g_Wph + (size_t)ch * 16 * SH_P);
        unsigned wdst = (unsigned)__cvta_generic_to_shared(&Wh[b][0]);
        if (t < 256) {
            int np = t / 20, seg = t % 20;
            CPA16(wdst + (unsigned)(np * 88 + seg * 4) * 4,
                  wsrc + (np * 80 + seg * 4) * 4);
        }
        if (t < 64) {
            int i2 = t + 256;
            int np = i2 / 20, seg = i2 % 20;
            CPA16(wdst + (unsigned)(np * 88 + seg * 4) * 4,
                  wsrc + (np * 80 + seg * 4) * 4);
        }
        unsigned xdst = (unsigned)__cvta_generic_to_shared(&Xs[b][0][0]);
        #pragma unroll
        for (int it = 0; it < 4; it++) {
            int idx = t + it * 256;
            int row = idx >> 5, seg = idx & 31;
            const char* xsrc = (const char*)(x + ((size_t)ch * 32 + row) * C_DIM + cbase + seg * 4);
            CPA16(xdst + (unsigned)(row * 140 + seg * 4) * 4, xsrc);
        }
    };

    issue(c0, 0);
    CPA_COMMIT();
    for (int ch = c0; ch < c1; ch++) {
        int buf = (ch - c0) & 1;
        if (ch + 1 < c1) issue(ch + 1, buf ^ 1);
        CPA_COMMIT();
        CPA_WAIT1();
        __syncthreads();
        #pragma unroll
        for (int kg = 0; kg < 2; kg++) {
            int rA = 2 * (kg * 8 + j);          // f32 row of even element
            int rB = rA + 8;                     // row of (pair+4) even element
            int col0 = w * 16 + q, col1 = col0 + 8;
            unsigned b0[2] = { pack_h2(Xs[buf][rA][col0], Xs[buf][rA + 1][col0]),
                               pack_h2(Xs[buf][rB][col0], Xs[buf][rB + 1][col0]) };
            unsigned b1[2] = { pack_h2(Xs[buf][rA][col1], Xs[buf][rA + 1][col1]),
                               pack_h2(Xs[buf][rB][col1], Xs[buf][rB + 1][col1]) };
            int rAp = kg * 8 + j, rBp = rAp + 4; // npair indices for W
            #pragma unroll
            for (int mt = 0; mt < 5; mt++) {
                int sh = mt * 16 + q;
                unsigned a[4];
                a[0] = Wh[buf][rAp * 88 + sh];
                a[1] = Wh[buf][rAp * 88 + sh + 8];
                a[2] = Wh[buf][rBp * 88 + sh];
                a[3] = Wh[buf][rBp * 88 + sh + 8];
                mma16h(acc[mt][0], a, b0);
                mma16h(acc[mt][1], a, b1);
            }
        }
        __syncthreads();
    }
    #pragma unroll
    for (int mt = 0; mt < 5; mt++) {
        int sh = mt * 16 + q;
        #pragma unroll
        for (int ct = 0; ct < 2; ct++) {
            int c = cbase + w * 16 + ct * 8 + 2 * j;
            if (sh < SH_N)
                red2(&g_u[sh * C_DIM + c], acc[mt][ct][0], acc[mt][ct][1]);
            if (sh + 8 < SH_N)
                red2(&g_u[(sh + 8) * C_DIM + c], acc[mt][ct][2], acc[mt][ct][3]);
        }
    }
}

// ubar[h][c] = w_nkv[c] * mean_s ( u[(s,h)][c] / Z[(s,h)] )
__global__ void k_ubar(const float* __restrict__ w_nkv, int S) {
    __shared__ float rzs[SH_N];
    int t = threadIdx.x;
    int i = blockIdx.x * 256 + t;
    if (t < SH_N) rzs[t] = 1.f / g_Z[t];
    __syncthreads();
    if (i >= H_DIM * C_DIM) return;
    int h = i >> 10, c = i & 1023;
    float s = 0.f;
    for (int si = 0; si < S; si++)
        s += g_u[(size_t)(si * H_DIM + h) * C_DIM + c] * rzs[si * H_DIM + h];
    g_ubar[i] = w_nkv[c] * s / (float)S;
}

// obar[j] = sum_c ubar[h][c] * Wv[2C+j][c] + bv[2C+j]
__global__ void k_obar(const float* __restrict__ ipw, const float* __restrict__ ipb) {
    __shared__ float red8[8];
    int j = blockIdx.x, t = threadIdx.x;
    int h = j >> 8;
    const float* wv = ipw + ((size_t)2 * C_DIM + j) * C_DIM;
    const float* ub = g_ubar + h * C_DIM;
    float acc = 0.f;
    for (int c = t; c < C_DIM; c += 256) acc += ub[c] * wv[c];
    float tot = block_reduce_sum(acc, red8);
    if (t == 0) g_obar[j] = tot + ipb[2 * C_DIM + j];
}

// out[c] = sanitize( sum_j obar[j] * Wout[c][j] + bout[c] )
__global__ void k_out(const float* __restrict__ opw, const float* __restrict__ opb,
                      float* __restrict__ out) {
    __shared__ float red8[8];
    int c = blockIdx.x, t = threadIdx.x;
    const float* wr = opw + (size_t)c * C_DIM;
    float acc = 0.f;
    for (int j = t; j < C_DIM; j += 256) acc += g_obar[j] * wr[j];
    float tot = block_reduce_sum(acc, red8);
    if (t == 0) out[c] = san(tot + opb[c]);
}

// ------------------------------- launcher ------------------------------------
extern "C" void kernel_launch(void* const* d_in, const int* in_sizes, int n_in,
                              void* d_out, int out_size) {
    const float* x     = (const float*)d_in[0];
    const float* seeds = (const float*)d_in[1];
    const float* w_nq  = (const float*)d_in[2];
    const float* w_nkv = (const float*)d_in[3];
    const float* ipw   = (const float*)d_in[4];
    const float* ipb   = (const float*)d_in[5];
    const float* opw   = (const float*)d_in[6];
    const float* opb   = (const float*)d_in[7];
    float* out = (float*)d_out;

    int N = in_sizes[0] / C_DIM;
    if (N > NCAP) N = NCAP;
    int S = in_sizes[1] / C_DIM;   // 18

    int half = (S + 1) >> 1;                          // 9
    int qp_sm = S * C_DIM * 4;                        // 73728
    int bm_sm = half * 4 * DH * 4 + 16 * 9 * 16 * 4;  // 36864 + 9216 = 46080
    cudaFuncSetAttribute(k_scores, cudaFuncAttributeMaxDynamicSharedMemorySize, SMEM_SC);
    cudaFuncSetAttribute(k_qp, cudaFuncAttributeMaxDynamicSharedMemorySize, qp_sm);
    cudaFuncSetAttribute(k_bmat, cudaFuncAttributeMaxDynamicSharedMemorySize, bm_sm);

    k_qp<<<C_DIM / 8, 256, qp_sm>>>(seeds, w_nq, ipw, ipb, S);
    k_bmat<<<dim3(C_DIM / 16, 2), 256, bm_sm>>>(ipw, w_nkv, S);
    k_scores<<<(N + 127) / 128, 256, SMEM_SC>>>(x, N);
    k_u<<<dim3(8, UY), 256>>>(x, N);
    k_ubar<<<(H_DIM * C_DIM + 255) / 256, 256>>>(w_nkv, S);
    k_obar<<<C_DIM, 256>>>(ipw, ipb);
    k_out<<<C_DIM, 256>>>(opw, opb, out);
}

// round 17
// speedup vs baseline: 1.1338x; 1.0668x over previous
#include <cuda_runtime.h>
#include <cuda_fp16.h>
#include <math.h>
#include <stdint.h>

#define CLAMP_V 10000.0f
#define EPS_V   1e-8f
#define C_DIM   1024
#define H_DIM   4
#define DH      256
#define S_MAX   18
#define SH_N    72          // S*H
#define SH_P    80          // padded to 5 m16 tiles
#define NCAP    100352
#define NPCAP   (NCAP/2)
#define NCH     (C_DIM/32)  // 32 k-chunks in pass 1

// ------------------------- device scratch (static, no allocs) ----------------
__device__ float    g_qp[S_MAX * C_DIM];
__device__ __align__(16) uint2    g_Bph[64 * SH_N * 4];           // fp16x2 B k-pairs [g][sh][j]
__device__ __align__(16) unsigned g_Wph[(size_t)NPCAP * SH_P];    // fp16x2 (w[2p], w[2p+1]) [npair][sh]
__device__ float    g_Z[SH_N];
__device__ float    g_u[SH_N * C_DIM];
__device__ float    g_ubar[H_DIM * C_DIM];
__device__ float    g_obar[C_DIM];

// ------------------------------- helpers -------------------------------------
__device__ __forceinline__ float san(float v) {
    if (!(v == v)) return 0.f;
    return fminf(fmaxf(v, -CLAMP_V), CLAMP_V);
}
__device__ __forceinline__ unsigned pack_h2(float lo, float hi) {
    unsigned r;
    asm("cvt.rn.f16x2.f32 %0, %1, %2;" : "=r"(r) : "f"(hi), "f"(lo));
    return r;
}
__device__ __forceinline__ void mma16h(float d[4], const unsigned a[4], const unsigned b[2]) {
    asm volatile(
        "mma.sync.aligned.m16n8k16.row.col.f32.f16.f16.f32 "
        "{%0,%1,%2,%3},{%4,%5,%6,%7},{%8,%9},{%0,%1,%2,%3};\n"
        : "+f"(d[0]), "+f"(d[1]), "+f"(d[2]), "+f"(d[3])
        : "r"(a[0]), "r"(a[1]), "r"(a[2]), "r"(a[3]), "r"(b[0]), "r"(b[1]));
}
__device__ __forceinline__ void red2(float* p, float a, float b) {
    asm volatile("red.global.add.v2.f32 [%0], {%1, %2};" :: "l"(p), "f"(a), "f"(b) : "memory");
}
#define CPA16(dst, src) asm volatile("cp.async.cg.shared.global [%0], [%1], 16;" :: "r"(dst), "l"(src))
#define CPA_COMMIT()    asm volatile("cp.async.commit_group;")
#define CPA_WAIT1()     asm volatile("cp.async.wait_group 1;" ::: "memory")

__device__ __forceinline__ float block_reduce_sum(float v, float* red8) {
    #pragma unroll
    for (int o = 16; o > 0; o >>= 1) v += __shfl_xor_sync(0xffffffffu, v, o);
    int w = threadIdx.x >> 5, lane = threadIdx.x & 31;
    if (lane == 0) red8[w] = v;
    __syncthreads();
    float tot = 0.f;
    #pragma unroll
    for (int i = 0; i < 8; i++) tot += red8[i];
    return tot;
}

// ------------------------------- kernels -------------------------------------
// qp[s][j] = ( rmsnorm(seeds[s], w_nq) . Wq[j] + bq[j] ) / 16
__global__ void __launch_bounds__(256) k_qp(const float* __restrict__ seeds,
                                            const float* __restrict__ w_nq,
                                            const float* __restrict__ ipw,
                                            const float* __restrict__ ipb, int S) {
    extern __shared__ __align__(16) float qs[];   // [S][1024]
    int t = threadIdx.x;
    int wj = t >> 5, lane = t & 31;
    for (int i = blockIdx.x * 256 + t; i < SH_N * C_DIM; i += 128 * 256) g_u[i] = 0.f;
    if (blockIdx.x == 0 && t < SH_N) g_Z[t] = 0.f;
    for (int s = wj; s < S; s += 8) {
        const float4* src = (const float4*)(seeds + (size_t)s * C_DIM);
        float4 v[8];
        float ssq = 0.f;
        #pragma unroll
        for (int i = 0; i < 8; i++) {
            float4 a = src[lane + i * 32];
            a.x = san(a.x); a.y = san(a.y); a.z = san(a.z); a.w = san(a.w);
            v[i] = a;
            ssq += a.x * a.x + a.y * a.y + a.z * a.z + a.w * a.w;
        }
        #pragma unroll
        for (int o = 16; o > 0; o >>= 1) ssq += __shfl_xor_sync(0xffffffffu, ssq, o);
        float inv = 1.f / (sqrtf(ssq) * (1.0f / 32.0f) + EPS_V);
        #pragma unroll
        for (int i = 0; i < 8; i++) {
            float4 wn = ((const float4*)w_nq)[lane + i * 32];
            float4 o = make_float4(v[i].x * wn.x * inv, v[i].y * wn.y * inv,
                                   v[i].z * wn.z * inv, v[i].w * wn.w * inv);
            ((float4*)(qs + s * C_DIM))[lane + i * 32] = o;
        }
    }
    __syncthreads();
    int j = blockIdx.x * 8 + wj;
    const float4* wr = (const float4*)(ipw + (size_t)j * C_DIM);
    float acc[S_MAX];
    #pragma unroll
    for (int s = 0; s < S_MAX; s++) acc[s] = 0.f;
    for (int c4 = 0; c4 < 8; c4++) {
        float4 a = wr[lane + c4 * 32];
        int cb = (lane + c4 * 32) * 4;
        for (int s = 0; s < S; s++) {
            float4 b = *(const float4*)&qs[s * C_DIM + cb];
            acc[s] += a.x * b.x + a.y * b.y + a.z * b.z + a.w * b.w;
        }
    }
    for (int s = 0; s < S; s++) {
        float v = acc[s];
        #pragma unroll
        for (int o = 16; o > 0; o >>= 1) v += __shfl_xor_sync(0xffffffffu, v, o);
        if (lane == 0) g_qp[s * C_DIM + j] = (v + ipb[j]) * 0.0625f;
    }
}

// B[sh][c] = w_nkv[c] * sum_d qp[s][h*DH+d] * Wk[h*DH+d][c]  -> fp16x2 k-pair frags
// Grid (64, 2): y splits the seed dimension for 2x parallelism.
__global__ void __launch_bounds__(256) k_bmat(const float* __restrict__ ipw,
                                              const float* __restrict__ w_nkv, int S) {
    extern __shared__ __align__(16) float sm[];
    int half = (S + 1) >> 1;                           // 9
    int s0 = blockIdx.y * half;
    int s1 = s0 + half; if (s1 > S) s1 = S;
    int ls = s1 - s0;
    float* qph = sm;                                   // [ls*4][256] : local sh-major
    float (*psum)[9][16] = (float (*)[9][16])(sm + (size_t)half * 4 * DH);
    int t = threadIdx.x;
    int c_l = t & 15, seg = t >> 4;
    int g = blockIdx.x;
    int cb = g * 16;
    for (int i = t; i < ls * 4 * DH; i += 256) {
        int sh = i >> 8, d = i & 255;
        int s = s0 + (sh >> 2), h = sh & 3;
        qph[i] = g_qp[s * C_DIM + h * DH + d];
    }
    __syncthreads();
    int h = seg >> 2;
    int dloc = (seg & 3) * 64;
    int dbase = h * DH + dloc;
    float acc[9];
    #pragma unroll
    for (int s = 0; s < 9; s++) acc[s] = 0.f;
    const float* wkb = ipw + ((size_t)C_DIM + dbase) * C_DIM + cb + c_l;
    for (int d4 = 0; d4 < 16; d4++) {
        int d0 = d4 * 4;
        float k0 = wkb[(size_t)(d0 + 0) * C_DIM];
        float k1 = wkb[(size_t)(d0 + 1) * C_DIM];
        float k2 = wkb[(size_t)(d0 + 2) * C_DIM];
        float k3 = wkb[(size_t)(d0 + 3) * C_DIM];
        for (int s = 0; s < ls; s++) {
            float4 q = *(const float4*)&qph[(s * 4 + h) * DH + dloc + d0];
            acc[s] += q.x * k0 + q.y * k1 + q.z * k2 + q.w * k3;
        }
    }
    for (int s = 0; s < ls; s++) psum[seg][s][c_l] = acc[s];
    __syncthreads();
    for (int p = t; p < ls * 4 * 4; p += 256) {
        int shl = p >> 2, j = p & 3;
        int sl = shl >> 2, hh = shl & 3;
        int sh = (s0 + sl) * 4 + hh;
        float v0 = 0.f, v1 = 0.f, v2 = 0.f, v3 = 0.f;
        #pragma unroll
        for (int k = 0; k < 4; k++) {
            v0 += psum[hh * 4 + k][sl][2 * j];
            v1 += psum[hh * 4 + k][sl][2 * j + 1];
            v2 += psum[hh * 4 + k][sl][2 * j + 8];
            v3 += psum[hh * 4 + k][sl][2 * j + 9];
        }
        v0 *= w_nkv[cb + 2 * j];     v1 *= w_nkv[cb + 2 * j + 1];
        v2 *= w_nkv[cb + 2 * j + 8]; v3 *= w_nkv[cb + 2 * j + 9];
        g_Bph[((size_t)g * SH_N + sh) * 4 + j] = make_uint2(pack_h2(v0, v1), pack_h2(v2, v3));
    }
}

// Pass 1: 128 rows/block, warp m16 tile, fp16 m16n8k16 MMA, 4 CTAs/SM.
// Xs stride 40 -> conflict-free A-fragment LDS.64 (8q+2j bank map).
#define XSTRIDE  40
#define XS_BYTES (2 * 128 * XSTRIDE * 4)            // 40960
#define BS_BYTES (2 * 2 * SH_N * 4 * 8)             // 9216
#define SMEM_SC  (XS_BYTES + BS_BYTES)              // 50176
__global__ void __launch_bounds__(256, 4) k_scores(const float* __restrict__ x, int N) {
    extern __shared__ __align__(16) char smem[];
    float (*Xs)[128][XSTRIDE] = (float (*)[128][XSTRIDE])smem;
    uint2 (*Bs)[2][SH_N][4] = (uint2 (*)[2][SH_N][4])(smem + XS_BYTES);
    __shared__ float zs[8][SH_N];
    int t = threadIdx.x, w = t >> 5, lane = t & 31;
    int q = lane >> 2, j = lane & 3;
    size_t base = (size_t)blockIdx.x * 128;
    size_t lastRow = (size_t)N - 1;
    int r0 = w * 16 + q;

    bool ok[2];
    ok[0] = (base + r0) < (size_t)N;
    ok[1] = (base + r0 + 8) < (size_t)N;

    float acc[9][4];
    #pragma unroll
    for (int n = 0; n < 9; n++)
        #pragma unroll
        for (int i = 0; i < 4; i++) acc[n][i] = 0.f;
    float ssq[2] = {0.f, 0.f};

    auto stage = [&](int ch, int b) {
        unsigned xd = (unsigned)__cvta_generic_to_shared(&Xs[b][0][0]);
        int k0 = ch * 32;
        #pragma unroll
        for (int it = 0; it < 4; it++) {
            int idx = t + it * 256;
            int row = idx >> 3, seg = idx & 7;
            size_t gr = base + row; if (gr > lastRow) gr = lastRow;
            CPA16(xd + (unsigned)(row * XSTRIDE + seg * 4) * 4,
                  (const char*)(x + gr * C_DIM + k0 + seg * 4));
        }
        const char* src = (const char*)(g_Bph + (size_t)ch * 2 * SH_N * 4);
        unsigned bd = (unsigned)__cvta_generic_to_shared(&(*Bs)[0][0][0]) + b * (BS_BYTES / 2);
        CPA16(bd + t * 16, src + t * 16);
        if (t < 32) CPA16(bd + (t + 256) * 16, src + (t + 256) * 16);
    };

    stage(0, 0);
    CPA_COMMIT();
    for (int ch = 0; ch < NCH; ch++) {
        int buf = ch & 1;
        if (ch + 1 < NCH) stage(ch + 1, buf ^ 1);
        CPA_COMMIT();
        CPA_WAIT1();
        __syncthreads();
        #pragma unroll
        for (int s = 0; s < 2; s++) {          // two k16 steps per 32-chunk
            int cb = s * 16 + 2 * j;
            float2 x00 = *(const float2*)&Xs[buf][r0][cb];
            float2 x01 = *(const float2*)&Xs[buf][r0][cb + 8];
            float2 x10 = *(const float2*)&Xs[buf][r0 + 8][cb];
            float2 x11 = *(const float2*)&Xs[buf][r0 + 8][cb + 8];
            ssq[0] += x00.x * x00.x + x00.y * x00.y + x01.x * x01.x + x01.y * x01.y;
            ssq[1] += x10.x * x10.x + x10.y * x10.y + x11.x * x11.x + x11.y * x11.y;
            unsigned a[4] = { pack_h2(x00.x, x00.y), pack_h2(x10.x, x10.y),
                              pack_h2(x01.x, x01.y), pack_h2(x11.x, x11.y) };
            #pragma unroll
            for (int nt = 0; nt < 9; nt++) {
                uint2 bb = Bs[buf][s][nt * 8 + q][j];
                unsigned b[2] = {bb.x, bb.y};
                mma16h(acc[nt], a, b);
            }
        }
        __syncthreads();
    }

    float inv[2];
    #pragma unroll
    for (int s = 0; s < 2; s++) {
        float sv = ssq[s];
        sv += __shfl_xor_sync(0xffffffffu, sv, 1);
        sv += __shfl_xor_sync(0xffffffffu, sv, 2);
        inv[s] = 1.f / (sqrtf(sv) * (1.0f / 32.0f) + EPS_V);
    }

    // epilogue: e = exp(score); adjacent-row fp16 pairs into g_Wph; Z partials
    size_t npair_b = (base >> 1) + (size_t)w * 8 + (q >> 1);
    bool evenq = (q & 1) == 0;
    #pragma unroll
    for (int nt = 0; nt < 9; nt++) {
        int c0 = nt * 8 + 2 * j;
        float e00 = ok[0] ? __expf(acc[nt][0] * inv[0]) : 0.f;
        float e01 = ok[0] ? __expf(acc[nt][1] * inv[0]) : 0.f;
        float e10 = ok[1] ? __expf(acc[nt][2] * inv[1]) : 0.f;
        float e11 = ok[1] ? __expf(acc[nt][3] * inv[1]) : 0.f;
        float z0 = e00 + e10, z1 = e01 + e11;
        float w00 = e00 * inv[0], w01 = e01 * inv[0];
        float w10 = e10 * inv[1], w11 = e11 * inv[1];
        float p00 = __shfl_xor_sync(0xffffffffu, w00, 4);
        float p01 = __shfl_xor_sync(0xffffffffu, w01, 4);
        float p10 = __shfl_xor_sync(0xffffffffu, w10, 4);
        float p11 = __shfl_xor_sync(0xffffffffu, w11, 4);
        if (evenq) {
            g_Wph[npair_b * SH_P + c0]       = pack_h2(w00, p00);
            g_Wph[(npair_b + 4) * SH_P + c0] = pack_h2(w10, p10);
        } else {
            g_Wph[npair_b * SH_P + c0 + 1]       = pack_h2(p01, w01);
            g_Wph[(npair_b + 4) * SH_P + c0 + 1] = pack_h2(p11, w11);
        }
        #pragma unroll
        for (int o = 4; o < 32; o <<= 1) {
            z0 += __shfl_xor_sync(0xffffffffu, z0, o);
            z1 += __shfl_xor_sync(0xffffffffu, z1, o);
        }
        if (q == 0) { zs[w][c0] = z0; zs[w][c0 + 1] = z1; }
    }
    __syncthreads();
    if (t < SH_N) {
        float z = 0.f;
        #pragma unroll
        for (int i = 0; i < 8; i++) z += zs[i][t];
        atomicAdd(&g_Z[t], z);
    }
}

// Pass 2: u[sh][c] += sum_n wp[sh,n] * xs[n,c].  32-row chunks, fp16 m16n8k16 MMA,
// W fp16 from smem, B-frags packed inline from f32 stage (stride 140: conflict-free).
#define UY 74
__global__ void __launch_bounds__(256, 4) k_u(const float* __restrict__ x, int N) {
    __shared__ __align__(16) unsigned Wh[2][16 * 88];   // fp16x2 [npair][sh] stride 88, 11 KB
    __shared__ __align__(16) float Xs[2][32][140];      // f32 staging, 35.8 KB
    int t = threadIdx.x, w = t >> 5, lane = t & 31;
    int q = lane >> 2, j = lane & 3;
    int cbase = blockIdx.x * 128;
    int TC = N >> 5;
    int c0 = (int)((long long)blockIdx.y * TC / UY);
    int c1 = (int)((long long)(blockIdx.y + 1) * TC / UY);
    float acc[5][2][4];
    #pragma unroll
    for (int i = 0; i < 5; i++)
        #pragma unroll
        for (int k = 0; k < 2; k++)
            #pragma unroll
            for (int l = 0; l < 4; l++) acc[i][k][l] = 0.f;

    auto issue = [&](int ch, int b) {
        const char* wsrc = (const char*)(g_Wph + (size_t)ch * 16 * SH_P);
        unsigned wdst = (unsigned)__cvta_generic_to_shared(&Wh[b][0]);
        if (t < 256) {
            int np = t / 20, seg = t % 20;
            CPA16(wdst + (unsigned)(np * 88 + seg * 4) * 4,
                  wsrc + (np * 80 + seg * 4) * 4);
        }
        if (t < 64) {
            int i2 = t + 256;
            int np = i2 / 20, seg = i2 % 20;
            CPA16(wdst + (unsigned)(np * 88 + seg * 4) * 4,
                  wsrc + (np * 80 + seg * 4) * 4);
        }
        unsigned xdst = (unsigned)__cvta_generic_to_shared(&Xs[b][0][0]);
        #pragma unroll
        for (int it = 0; it < 4; it++) {
            int idx = t + it * 256;
            int row = idx >> 5, seg = idx & 31;
            const char* xsrc = (const char*)(x + ((size_t)ch * 32 + row) * C_DIM + cbase + seg * 4);
            CPA16(xdst + (unsigned)(row * 140 + seg * 4) * 4, xsrc);
        }
    };

    issue(c0, 0);
    CPA_COMMIT();
    for (int ch = c0; ch < c1; ch++) {
        int buf = (ch - c0) & 1;
        if (ch + 1 < c1) issue(ch + 1, buf ^ 1);
        CPA_COMMIT();
        CPA_WAIT1();
        __syncthreads();
        #pragma unroll
        for (int kg = 0; kg < 2; kg++) {
            int rA = 2 * (kg * 8 + j);          // f32 row of even element
            int rB = rA + 8;                     // row of (pair+4) even element
            int col0 = w * 16 + q, col1 = col0 + 8;
            unsigned b0[2] = { pack_h2(Xs[buf][rA][col0], Xs[buf][rA + 1][col0]),
                               pack_h2(Xs[buf][rB][col0], Xs[buf][rB + 1][col0]) };
            unsigned b1[2] = { pack_h2(Xs[buf][rA][col1], Xs[buf][rA + 1][col1]),
                               pack_h2(Xs[buf][rB][col1], Xs[buf][rB + 1][col1]) };
            int rAp = kg * 8 + j, rBp = rAp + 4; // npair indices for W
            #pragma unroll
            for (int mt = 0; mt < 5; mt++) {
                int sh = mt * 16 + q;
                unsigned a[4];
                a[0] = Wh[buf][rAp * 88 + sh];
                a[1] = Wh[buf][rAp * 88 + sh + 8];
                a[2] = Wh[buf][rBp * 88 + sh];
                a[3] = Wh[buf][rBp * 88 + sh + 8];
                mma16h(acc[mt][0], a, b0);
                mma16h(acc[mt][1], a, b1);
            }
        }
        __syncthreads();
    }
    #pragma unroll
    for (int mt = 0; mt < 5; mt++) {
        int sh = mt * 16 + q;
        #pragma unroll
        for (int ct = 0; ct < 2; ct++) {
            int c = cbase + w * 16 + ct * 8 + 2 * j;
            if (sh < SH_N)
                red2(&g_u[sh * C_DIM + c], acc[mt][ct][0], acc[mt][ct][1]);
            if (sh + 8 < SH_N)
                red2(&g_u[(sh + 8) * C_DIM + c], acc[mt][ct][2], acc[mt][ct][3]);
        }
    }
}

// ubar[h][c] = w_nkv[c] * mean_s ( u[(s,h)][c] / Z[(s,h)] )
__global__ void k_ubar(const float* __restrict__ w_nkv, int S) {
    __shared__ float rzs[SH_N];
    int t = threadIdx.x;
    int i = blockIdx.x * 256 + t;
    if (t < SH_N) rzs[t] = 1.f / g_Z[t];
    __syncthreads();
    if (i >= H_DIM * C_DIM) return;
    int h = i >> 10, c = i & 1023;
    float s = 0.f;
    for (int si = 0; si < S; si++)
        s += g_u[(size_t)(si * H_DIM + h) * C_DIM + c] * rzs[si * H_DIM + h];
    g_ubar[i] = w_nkv[c] * s / (float)S;
}

// obar[j] = sum_c ubar[h][c] * Wv[2C+j][c] + bv[2C+j]
__global__ void k_obar(const float* __restrict__ ipw, const float* __restrict__ ipb) {
    __shared__ float red8[8];
    int j = blockIdx.x, t = threadIdx.x;
    int h = j >> 8;
    const float* wv = ipw + ((size_t)2 * C_DIM + j) * C_DIM;
    const float* ub = g_ubar + h * C_DIM;
    float acc = 0.f;
    for (int c = t; c < C_DIM; c += 256) acc += ub[c] * wv[c];
    float tot = block_reduce_sum(acc, red8);
    if (t == 0) g_obar[j] = tot + ipb[2 * C_DIM + j];
}

// out[c] = sanitize( sum_j obar[j] * Wout[c][j] + bout[c] )
__global__ void k_out(const float* __restrict__ opw, const float* __restrict__ opb,
                      float* __restrict__ out) {
    __shared__ float red8[8];
    int c = blockIdx.x, t = threadIdx.x;
    const float* wr = opw + (size_t)c * C_DIM;
    float acc = 0.f;
    for (int j = t; j < C_DIM; j += 256) acc += g_obar[j] * wr[j];
    float tot = block_reduce_sum(acc, red8);
    if (t == 0) out[c] = san(tot + opb[c]);
}

// ------------------------------- launcher ------------------------------------
extern "C" void kernel_launch(void* const* d_in, const int* in_sizes, int n_in,
                              void* d_out, int out_size) {
    const float* x     = (const float*)d_in[0];
    const float* seeds = (const float*)d_in[1];
    const float* w_nq  = (const float*)d_in[2];
    const float* w_nkv = (const float*)d_in[3];
    const float* ipw   = (const float*)d_in[4];
    const float* ipb   = (const float*)d_in[5];
    const float* opw   = (const float*)d_in[6];
    const float* opb   = (const float*)d_in[7];
    float* out = (float*)d_out;

    int N = in_sizes[0] / C_DIM;
    if (N > NCAP) N = NCAP;
    int S = in_sizes[1] / C_DIM;   // 18

    int half = (S + 1) >> 1;                          // 9
    int qp_sm = S * C_DIM * 4;                        // 73728
    int bm_sm = half * 4 * DH * 4 + 16 * 9 * 16 * 4;  // 46080
    cudaFuncSetAttribute(k_scores, cudaFuncAttributeMaxDynamicSharedMemorySize, SMEM_SC);
    cudaFuncSetAttribute(k_qp, cudaFuncAttributeMaxDynamicSharedMemorySize, qp_sm);
    cudaFuncSetAttribute(k_bmat, cudaFuncAttributeMaxDynamicSharedMemorySize, bm_sm);

    k_qp<<<C_DIM / 8, 256, qp_sm>>>(seeds, w_nq, ipw, ipb, S);
    k_bmat<<<dim3(C_DIM / 16, 2), 256, bm_sm>>>(ipw, w_nkv, S);
    k_scores<<<(N + 127) / 128, 256, SMEM_SC>>>(x, N);
    k_u<<<dim3(8, UY), 256>>>(x, N);
    k_ubar<<<(H_DIM * C_DIM + 255) / 256, 256>>>(w_nkv, S);
    k_obar<<<C_DIM, 256>>>(ipw, ipb);
    k_out<<<C_DIM, 256>>>(opw, opb, out);
}